// round 2
// baseline (speedup 1.0000x reference)
#include <cuda_runtime.h>
#include <cuda_bf16.h>
#include <cstdint>

// Problem constants (from reference)
#define NB    512
#define NM    2048
#define TOTAL (NB*NM)          // 1,048,576
#define NUM_KEYS  1000000
#define NUM_NODES 100000
#define LP   4
#define ENC  32
#define FEAT 64
#define D3   64

// ---------------- scratch (device globals; no cudaMalloc allowed) ----------------
__device__ __align__(16) float g_featc[(size_t)NUM_NODES * D3];  // feat @ Wm1b + bm1 + b2@Wm1a  (25.6 MB)
__device__ __align__(16) float g_wfused[ENC * D3];               // W2 @ Wm1[:32]   [32][64]
__device__ __align__(16) float g_cvec[D3];                       // bm1 + b2 @ Wm1[:32]

// ---------------- f32x2 helpers (sm_103a packed fp32) ----------------
__device__ __forceinline__ unsigned long long pk2(float a, float b) {
    unsigned long long r;
    asm("mov.b64 %0, {%1, %2};" : "=l"(r) : "f"(a), "f"(b));
    return r;
}
__device__ __forceinline__ void upk2(unsigned long long v, float& a, float& b) {
    asm("mov.b64 {%0, %1}, %2;" : "=f"(a), "=f"(b) : "l"(v));
}
__device__ __forceinline__ unsigned long long fma2(unsigned long long a, unsigned long long b,
                                                   unsigned long long c) {
    unsigned long long d;
    asm("fma.rn.f32x2 %0, %1, %2, %3;" : "=l"(d) : "l"(a), "l"(b), "l"(c));
    return d;
}

// ---------------- kernel C: fold weights ----------------
// g_wfused[j][d] = sum_c W2[j][c] * Wm1[c][d]          (j<32, d<64)
// g_cvec[d]      = bm1[d] + sum_c b2[c] * Wm1[c][d]
__global__ void fold_weights_kernel(const float* __restrict__ W2,
                                    const float* __restrict__ Wm1,
                                    const float* __restrict__ b2,
                                    const float* __restrict__ bm1) {
    int t = blockIdx.x * blockDim.x + threadIdx.x;
    if (t < ENC * D3) {
        int j = t >> 6, d = t & 63;
        float s = 0.f;
#pragma unroll
        for (int c = 0; c < ENC; c++) s = fmaf(W2[j * ENC + c], Wm1[c * D3 + d], s);
        g_wfused[t] = s;
    } else if (t < ENC * D3 + D3) {
        int d = t - ENC * D3;
        float s = bm1[d];
#pragma unroll
        for (int c = 0; c < ENC; c++) s = fmaf(b2[c], Wm1[c * D3 + d], s);
        g_cvec[d] = s;
    }
}

// ---------------- kernel A: per-node precompute ----------------
// g_featc[n][d] = g_cvec[d] + sum_k node_feat[n][k] * Wm1[32+k][d]
// 64 nodes per block. blockDim = 256 = 16 col-quads x 16 row-groups.
__global__ __launch_bounds__(256) void node_precompute_kernel(
    const float* __restrict__ node_feat, const float* __restrict__ Wm1) {
    __shared__ float sW[FEAT * D3];   // Wm1 bottom half [64][64], 16 KB
    __shared__ float sF[64 * FEAT];   // 64 feature rows, 16 KB
    __shared__ float sc[D3];

    int t = threadIdx.x;
    int n0 = blockIdx.x * 64;

    for (int i = t; i < FEAT * D3; i += 256) sW[i] = Wm1[ENC * D3 + i];
    if (t < D3) sc[t] = g_cvec[t];
    for (int i = t; i < 64 * FEAT; i += 256) {
        int r = i >> 6;
        int n = n0 + r;
        sF[i] = (n < NUM_NODES) ? node_feat[(size_t)n * FEAT + (i & 63)] : 0.f;
    }
    __syncthreads();

    int cq = (t & 15) * 4;  // 4 output columns per thread
    int rg = t >> 4;        // row group 0..15
    for (int r = rg; r < 64; r += 16) {
        unsigned long long acc0 = pk2(sc[cq], sc[cq + 1]);
        unsigned long long acc1 = pk2(sc[cq + 2], sc[cq + 3]);
        const float* frow = &sF[r * FEAT];
#pragma unroll
        for (int k = 0; k < FEAT; k++) {
            unsigned long long ff = pk2(frow[k], frow[k]);
            const ulonglong2* w = (const ulonglong2*)&sW[k * D3 + cq];
            ulonglong2 ww = *w;
            acc0 = fma2(ff, ww.x, acc0);
            acc1 = fma2(ff, ww.y, acc1);
        }
        int n = n0 + r;
        if (n < NUM_NODES) {
            float a, b, c, d;
            upk2(acc0, a, b);
            upk2(acc1, c, d);
            *((float4*)&g_featc[(size_t)n * D3 + cq]) = make_float4(a, b, c, d);
        }
    }
}

// ---------------- kernel B: main fused per-element kernel ----------------
// one thread per (b, m) element:
//   enc  = pos_table[key_idx[e]]                      (float4 gather)
//   a_j  = relu(b1_j + enc . W1[:,j])                 (j < 32)
//   h    = g_featc[node_idx[e]] + sum_j a_j * Wfused[j]   (64-wide, f32x2 regs)
//   z    = bm2 + sum relu(h) * Wm2
__global__ __launch_bounds__(256) void main_kernel(
    const float* __restrict__ pos_table,
    const int* __restrict__ key_idx,
    const int* __restrict__ node_idx,
    const float* __restrict__ W1,
    const float* __restrict__ b1,
    const float* __restrict__ Wm2,
    const float* __restrict__ bm2,
    float* __restrict__ out, int total) {
    __shared__ float4 sW1t[ENC];                       // W1 transposed: [j] -> (W1[0][j]..W1[3][j])
    __shared__ float sb1[ENC];
    __shared__ __align__(16) unsigned long long sWf[ENC * D3 / 2];  // Wfused rows packed f32x2
    __shared__ float sWm2[D3];
    __shared__ float sbm2;

    int t = threadIdx.x;
    {
        const unsigned long long* gwf = (const unsigned long long*)g_wfused;
        for (int i = t; i < ENC * D3 / 2; i += 256) sWf[i] = gwf[i];
        if (t < ENC) {
            sb1[t] = b1[t];
            sW1t[t] = make_float4(W1[0 * ENC + t], W1[1 * ENC + t], W1[2 * ENC + t], W1[3 * ENC + t]);
        }
        if (t < D3) sWm2[t] = Wm2[t];
        if (t == 0) sbm2 = bm2[0];
    }
    __syncthreads();

    int e = blockIdx.x * 256 + t;
    if (e >= total) return;

    int k = __ldg(key_idx + e);
    int n = __ldg(node_idx + e);

    float4 enc = __ldg(((const float4*)pos_table) + k);

    // h accumulators: 64 floats as 32 packed f32x2
    unsigned long long h[D3 / 2];
    {
        const float4* fr = (const float4*)(g_featc + (size_t)n * D3);
#pragma unroll
        for (int q = 0; q < 16; q++) {
            float4 v = __ldg(fr + q);
            h[2 * q]     = pk2(v.x, v.y);
            h[2 * q + 1] = pk2(v.z, v.w);
        }
    }

#pragma unroll
    for (int j = 0; j < ENC; j++) {
        float4 w = sW1t[j];
        float aj = sb1[j];
        aj = fmaf(enc.x, w.x, aj);
        aj = fmaf(enc.y, w.y, aj);
        aj = fmaf(enc.z, w.z, aj);
        aj = fmaf(enc.w, w.w, aj);
        aj = fmaxf(aj, 0.0f);
        unsigned long long aa = pk2(aj, aj);
        const ulonglong2* wr = (const ulonglong2*)&sWf[j * (D3 / 2)];
#pragma unroll
        for (int q = 0; q < 16; q++) {
            ulonglong2 ww = wr[q];
            h[2 * q]     = fma2(aa, ww.x, h[2 * q]);
            h[2 * q + 1] = fma2(aa, ww.y, h[2 * q + 1]);
        }
    }

    float z = sbm2;
#pragma unroll
    for (int p = 0; p < D3 / 2; p++) {
        float x, y;
        upk2(h[p], x, y);
        z = fmaf(fmaxf(x, 0.0f), sWm2[2 * p], z);
        z = fmaf(fmaxf(y, 0.0f), sWm2[2 * p + 1], z);
    }
    out[e] = z;
}

// ---------------- launch ----------------
extern "C" void kernel_launch(void* const* d_in, const int* in_sizes, int n_in,
                              void* d_out, int out_size) {
    const float* pos_table = (const float*)d_in[0];
    const float* node_feat = (const float*)d_in[1];
    const float* W1  = (const float*)d_in[2];
    const float* b1  = (const float*)d_in[3];
    const float* W2  = (const float*)d_in[4];
    const float* b2  = (const float*)d_in[5];
    const float* Wm1 = (const float*)d_in[6];
    const float* bm1 = (const float*)d_in[7];
    const float* Wm2 = (const float*)d_in[8];
    const float* bm2 = (const float*)d_in[9];
    const int* key_idx  = (const int*)d_in[10];
    const int* node_idx = (const int*)d_in[11];
    float* out = (float*)d_out;

    // Fold weights: 2048 + 64 outputs
    fold_weights_kernel<<<(ENC * D3 + D3 + 255) / 256, 256>>>(W2, Wm1, b2, bm1);

    // Per-node precompute: 64 nodes/block
    node_precompute_kernel<<<(NUM_NODES + 63) / 64, 256>>>(node_feat, Wm1);

    // Main fused kernel
    int total = out_size;
    main_kernel<<<(total + 255) / 256, 256>>>(pos_table, key_idx, node_idx,
                                              W1, b1, Wm2, bm2, out, total);
}

// round 3
// speedup vs baseline: 1.0057x; 1.0057x over previous
#include <cuda_runtime.h>
#include <cuda_bf16.h>
#include <cstdint>

// Problem constants (from reference)
#define NB    512
#define NM    2048
#define TOTAL (NB*NM)          // 1,048,576
#define NUM_KEYS  1000000
#define NUM_NODES 100000
#define LP   4
#define ENC  32
#define FEAT 64
#define D3   64

// ---------------- scratch (device globals; no cudaMalloc allowed) ----------------
__device__ __align__(16) float g_featc[(size_t)NUM_NODES * D3];  // feat @ Wm1b + bm1 + b2@Wm1a  (25.6 MB)
__device__ __align__(16) float g_wfused[ENC * D3];               // W2 @ Wm1[:32]   [32][64]
__device__ __align__(16) float g_cvec[D3];                       // bm1 + b2 @ Wm1[:32]

// ---------------- f32x2 helpers (sm_103a packed fp32) ----------------
__device__ __forceinline__ unsigned long long pk2(float a, float b) {
    unsigned long long r;
    asm("mov.b64 %0, {%1, %2};" : "=l"(r) : "f"(a), "f"(b));
    return r;
}
__device__ __forceinline__ void upk2(unsigned long long v, float& a, float& b) {
    asm("mov.b64 {%0, %1}, %2;" : "=f"(a), "=f"(b) : "l"(v));
}
__device__ __forceinline__ unsigned long long fma2(unsigned long long a, unsigned long long b,
                                                   unsigned long long c) {
    unsigned long long d;
    asm("fma.rn.f32x2 %0, %1, %2, %3;" : "=l"(d) : "l"(a), "l"(b), "l"(c));
    return d;
}

// ---------------- kernel C: fold weights ----------------
// g_wfused[j][d] = sum_c W2[j][c] * Wm1[c][d]          (j<32, d<64)
// g_cvec[d]      = bm1[d] + sum_c b2[c] * Wm1[c][d]
__global__ void fold_weights_kernel(const float* __restrict__ W2,
                                    const float* __restrict__ Wm1,
                                    const float* __restrict__ b2,
                                    const float* __restrict__ bm1) {
    int t = blockIdx.x * blockDim.x + threadIdx.x;
    if (t < ENC * D3) {
        int j = t >> 6, d = t & 63;
        float s = 0.f;
#pragma unroll
        for (int c = 0; c < ENC; c++) s = fmaf(W2[j * ENC + c], Wm1[c * D3 + d], s);
        g_wfused[t] = s;
    } else if (t < ENC * D3 + D3) {
        int d = t - ENC * D3;
        float s = bm1[d];
#pragma unroll
        for (int c = 0; c < ENC; c++) s = fmaf(b2[c], Wm1[c * D3 + d], s);
        g_cvec[d] = s;
    }
}

// ---------------- kernel A: per-node precompute ----------------
// g_featc[n][d] = g_cvec[d] + sum_k node_feat[n][k] * Wm1[32+k][d]
// 64 nodes per block. blockDim = 256 = 16 col-quads x 16 row-groups.
__global__ __launch_bounds__(256) void node_precompute_kernel(
    const float* __restrict__ node_feat, const float* __restrict__ Wm1) {
    __shared__ float sW[FEAT * D3];   // Wm1 bottom half [64][64], 16 KB
    __shared__ float sF[64 * FEAT];   // 64 feature rows, 16 KB
    __shared__ float sc[D3];

    int t = threadIdx.x;
    int n0 = blockIdx.x * 64;

    for (int i = t; i < FEAT * D3; i += 256) sW[i] = Wm1[ENC * D3 + i];
    if (t < D3) sc[t] = g_cvec[t];
    for (int i = t; i < 64 * FEAT; i += 256) {
        int r = i >> 6;
        int n = n0 + r;
        sF[i] = (n < NUM_NODES) ? node_feat[(size_t)n * FEAT + (i & 63)] : 0.f;
    }
    __syncthreads();

    int cq = (t & 15) * 4;  // 4 output columns per thread
    int rg = t >> 4;        // row group 0..15
    for (int r = rg; r < 64; r += 16) {
        unsigned long long acc0 = pk2(sc[cq], sc[cq + 1]);
        unsigned long long acc1 = pk2(sc[cq + 2], sc[cq + 3]);
        const float* frow = &sF[r * FEAT];
#pragma unroll
        for (int k = 0; k < FEAT; k++) {
            unsigned long long ff = pk2(frow[k], frow[k]);
            const ulonglong2* w = (const ulonglong2*)&sW[k * D3 + cq];
            ulonglong2 ww = *w;
            acc0 = fma2(ff, ww.x, acc0);
            acc1 = fma2(ff, ww.y, acc1);
        }
        int n = n0 + r;
        if (n < NUM_NODES) {
            float a, b, c, d;
            upk2(acc0, a, b);
            upk2(acc1, c, d);
            *((float4*)&g_featc[(size_t)n * D3 + cq]) = make_float4(a, b, c, d);
        }
    }
}

// ---------------- kernel B: main fused per-element kernel ----------------
// one thread per (b, m) element:
//   enc  = pos_table[key_idx[e]]                      (float4 gather)
//   a_j  = relu(b1_j + enc . W1[:,j])                 (j < 32)
//   h    = g_featc[node_idx[e]] + sum_j a_j * Wfused[j]   (64-wide, f32x2 regs)
//   z    = bm2 + sum relu(h) * Wm2
__global__ __launch_bounds__(256) void main_kernel(
    const float* __restrict__ pos_table,
    const int* __restrict__ key_idx,
    const int* __restrict__ node_idx,
    const float* __restrict__ W1,
    const float* __restrict__ b1,
    const float* __restrict__ Wm2,
    const float* __restrict__ bm2,
    float* __restrict__ out, int total) {
    __shared__ float4 sW1t[ENC];                       // W1 transposed: [j] -> (W1[0][j]..W1[3][j])
    __shared__ float sb1[ENC];
    __shared__ __align__(16) unsigned long long sWf[ENC * D3 / 2];  // Wfused rows packed f32x2
    __shared__ float sWm2[D3];
    __shared__ float sbm2;

    int t = threadIdx.x;
    {
        const unsigned long long* gwf = (const unsigned long long*)g_wfused;
        for (int i = t; i < ENC * D3 / 2; i += 256) sWf[i] = gwf[i];
        if (t < ENC) {
            sb1[t] = b1[t];
            sW1t[t] = make_float4(W1[0 * ENC + t], W1[1 * ENC + t], W1[2 * ENC + t], W1[3 * ENC + t]);
        }
        if (t < D3) sWm2[t] = Wm2[t];
        if (t == 0) sbm2 = bm2[0];
    }
    __syncthreads();

    int e = blockIdx.x * 256 + t;
    if (e >= total) return;

    int k = __ldg(key_idx + e);
    int n = __ldg(node_idx + e);

    float4 enc = __ldg(((const float4*)pos_table) + k);

    // h accumulators: 64 floats as 32 packed f32x2
    unsigned long long h[D3 / 2];
    {
        const float4* fr = (const float4*)(g_featc + (size_t)n * D3);
#pragma unroll
        for (int q = 0; q < 16; q++) {
            float4 v = __ldg(fr + q);
            h[2 * q]     = pk2(v.x, v.y);
            h[2 * q + 1] = pk2(v.z, v.w);
        }
    }

#pragma unroll
    for (int j = 0; j < ENC; j++) {
        float4 w = sW1t[j];
        float aj = sb1[j];
        aj = fmaf(enc.x, w.x, aj);
        aj = fmaf(enc.y, w.y, aj);
        aj = fmaf(enc.z, w.z, aj);
        aj = fmaf(enc.w, w.w, aj);
        aj = fmaxf(aj, 0.0f);
        unsigned long long aa = pk2(aj, aj);
        const ulonglong2* wr = (const ulonglong2*)&sWf[j * (D3 / 2)];
#pragma unroll
        for (int q = 0; q < 16; q++) {
            ulonglong2 ww = wr[q];
            h[2 * q]     = fma2(aa, ww.x, h[2 * q]);
            h[2 * q + 1] = fma2(aa, ww.y, h[2 * q + 1]);
        }
    }

    float z = sbm2;
#pragma unroll
    for (int p = 0; p < D3 / 2; p++) {
        float x, y;
        upk2(h[p], x, y);
        z = fmaf(fmaxf(x, 0.0f), sWm2[2 * p], z);
        z = fmaf(fmaxf(y, 0.0f), sWm2[2 * p + 1], z);
    }
    out[e] = z;
}

// ---------------- launch ----------------
extern "C" void kernel_launch(void* const* d_in, const int* in_sizes, int n_in,
                              void* d_out, int out_size) {
    const float* pos_table = (const float*)d_in[0];
    const float* node_feat = (const float*)d_in[1];
    const float* W1  = (const float*)d_in[2];
    const float* b1  = (const float*)d_in[3];
    const float* W2  = (const float*)d_in[4];
    const float* b2  = (const float*)d_in[5];
    const float* Wm1 = (const float*)d_in[6];
    const float* bm1 = (const float*)d_in[7];
    const float* Wm2 = (const float*)d_in[8];
    const float* bm2 = (const float*)d_in[9];
    const int* key_idx  = (const int*)d_in[10];
    const int* node_idx = (const int*)d_in[11];
    float* out = (float*)d_out;

    // Fold weights: 2048 + 64 outputs
    fold_weights_kernel<<<(ENC * D3 + D3 + 255) / 256, 256>>>(W2, Wm1, b2, bm1);

    // Per-node precompute: 64 nodes/block
    node_precompute_kernel<<<(NUM_NODES + 63) / 64, 256>>>(node_feat, Wm1);

    // Main fused kernel
    int total = out_size;
    main_kernel<<<(total + 255) / 256, 256>>>(pos_table, key_idx, node_idx,
                                              W1, b1, Wm2, bm2, out, total);
}

// round 6
// speedup vs baseline: 1.0146x; 1.0089x over previous
#include <cuda_runtime.h>
#include <cuda_bf16.h>
#include <cstdint>

#define NUM_KEYS  1000000
#define NUM_NODES 100000
#define LP   4
#define ENC  32
#define FEAT 64
#define D3   64

// ---------------- scratch (device globals) ----------------
__device__ __align__(16) float g_featc[(size_t)NUM_NODES * D3];  // feat@Wm1b + bm1 + b2@Wm1a (25.6MB)
__device__ __align__(16) float g_wfused[ENC * D3];               // W2 @ Wm1[:32]

// ---------------- f32x2 helpers ----------------
__device__ __forceinline__ unsigned long long pk2(float a, float b) {
    unsigned long long r;
    asm("mov.b64 %0, {%1, %2};" : "=l"(r) : "f"(a), "f"(b));
    return r;
}
__device__ __forceinline__ void upk2(unsigned long long v, float& a, float& b) {
    asm("mov.b64 {%0, %1}, %2;" : "=f"(a), "=f"(b) : "l"(v));
}
__device__ __forceinline__ unsigned long long fma2(unsigned long long a, unsigned long long b,
                                                   unsigned long long c) {
    unsigned long long d;
    asm("fma.rn.f32x2 %0, %1, %2, %3;" : "=l"(d) : "l"(a), "l"(b), "l"(c));
    return d;
}

// ---------------- kernel A: per-node precompute (+ weight fold in block 0) ----------------
__global__ __launch_bounds__(256) void node_precompute_kernel(
    const float* __restrict__ node_feat, const float* __restrict__ Wm1,
    const float* __restrict__ W2, const float* __restrict__ b2,
    const float* __restrict__ bm1) {
    __shared__ float sW[FEAT * D3];   // Wm1 bottom half [64][64]
    __shared__ float sF[64 * FEAT];   // 64 feature rows
    __shared__ float sc[D3];

    int t = threadIdx.x;
    int n0 = blockIdx.x * 64;

    for (int i = t; i < FEAT * D3; i += 256) sW[i] = Wm1[ENC * D3 + i];
    if (t < D3) {
        float s = bm1[t];
#pragma unroll
        for (int c = 0; c < ENC; c++) s = fmaf(b2[c], Wm1[c * D3 + t], s);
        sc[t] = s;
    }
    for (int i = t; i < 64 * FEAT; i += 256) {
        int r = i >> 6;
        int n = n0 + r;
        sF[i] = (n < NUM_NODES) ? node_feat[(size_t)n * FEAT + (i & 63)] : 0.f;
    }
    // block 0 additionally folds Wfused = W2 @ Wm1[:32]
    if (blockIdx.x == 0) {
#pragma unroll
        for (int p = t; p < ENC * D3; p += 256) {
            int j = p >> 6, d = p & 63;
            float s = 0.f;
#pragma unroll
            for (int c = 0; c < ENC; c++) s = fmaf(W2[j * ENC + c], Wm1[c * D3 + d], s);
            g_wfused[p] = s;
        }
    }
    __syncthreads();

    int cq = (t & 15) * 4;  // 4 output columns per thread
    int rg = t >> 4;        // row group
    for (int r = rg; r < 64; r += 16) {
        unsigned long long acc0 = pk2(sc[cq], sc[cq + 1]);
        unsigned long long acc1 = pk2(sc[cq + 2], sc[cq + 3]);
        const float* frow = &sF[r * FEAT];
#pragma unroll
        for (int k = 0; k < FEAT; k++) {
            unsigned long long ff = pk2(frow[k], frow[k]);
            ulonglong2 ww = *(const ulonglong2*)&sW[k * D3 + cq];
            acc0 = fma2(ff, ww.x, acc0);
            acc1 = fma2(ff, ww.y, acc1);
        }
        int n = n0 + r;
        if (n < NUM_NODES) {
            float a, b, c, d;
            upk2(acc0, a, b);
            upk2(acc1, c, d);
            *((float4*)&g_featc[(size_t)n * D3 + cq]) = make_float4(a, b, c, d);
        }
    }
}

// ---------------- kernel B: main fused kernel ----------------
// dynamic smem layout (bytes):
//   [0, 8192)       sWf  : ull[1024]  Wfused rows packed f32x2
//   [8192, 8704)    sW1t : float4[32]
//   [8704, 8832)    sb1  : float[32]
//   [8832, 9088)    sWm2 : float[64]
//   [9088, 9104)    sbm2
//   [9216, 10240)   sNod : int[256]
//   [10240, 77824)  sbuf : 256 rows x 66 floats (staged featc)
#define SMEM_BYTES 77824
#define RSTR 66

__global__ __launch_bounds__(256, 2) void main_kernel(
    const float* __restrict__ pos_table,
    const int* __restrict__ key_idx,
    const int* __restrict__ node_idx,
    const float* __restrict__ W1,
    const float* __restrict__ b1,
    const float* __restrict__ Wm2,
    const float* __restrict__ bm2,
    float* __restrict__ out, int total) {
    extern __shared__ char smemraw[];
    unsigned long long* sWf = (unsigned long long*)smemraw;
    float4* sW1t = (float4*)(smemraw + 8192);
    float*  sb1  = (float*)(smemraw + 8704);
    float*  sWm2 = (float*)(smemraw + 8832);
    float*  sbm2 = (float*)(smemraw + 9088);
    int*    sNod = (int*)(smemraw + 9216);
    float*  sbuf = (float*)(smemraw + 10240);

    int t = threadIdx.x;
    int e = blockIdx.x * 256 + t;
    int ec = e < total ? e : total - 1;

    // own-element loads early (latency hidden under weight setup)
    int k = __ldg(key_idx + ec);
    sNod[t] = __ldg(node_idx + ec);
    float4 enc = __ldg(((const float4*)pos_table) + k);

    // weights to smem
    {
        const unsigned long long* gwf = (const unsigned long long*)g_wfused;
#pragma unroll
        for (int i = t; i < ENC * D3 / 2; i += 256) sWf[i] = gwf[i];
        if (t < ENC) {
            sb1[t] = b1[t];
            sW1t[t] = make_float4(W1[t], W1[ENC + t], W1[2 * ENC + t], W1[3 * ENC + t]);
        } else if (t < ENC + D3) {
            sWm2[t - ENC] = Wm2[t - ENC];
        } else if (t == ENC + D3) {
            sbm2[0] = bm2[0];
        }
    }
    __syncthreads();

    // ---- coalesced cooperative stage of 256 featc rows ----
    const float4* gfc = (const float4*)g_featc;
#pragma unroll
    for (int i = 0; i < 16; i++) {
        int c = t + 256 * i;        // 0..4095
        int r = c >> 4;             // row 0..255
        int q = c & 15;             // float4 chunk within row
        int rn = sNod[r];
        float4 v = __ldg(gfc + (size_t)rn * 16 + q);
        float2* dst = (float2*)&sbuf[r * RSTR + q * 4];
        dst[0] = make_float2(v.x, v.y);
        dst[1] = make_float2(v.z, v.w);
    }
    __syncthreads();

    // h accumulators from own staged row (2-way max conflict LDS.64)
    unsigned long long h[D3 / 2];
    {
        const float2* myrow = (const float2*)&sbuf[t * RSTR];
#pragma unroll
        for (int p = 0; p < D3 / 2; p++) {
            float2 v = myrow[p];
            h[p] = pk2(v.x, v.y);
        }
    }

#pragma unroll
    for (int j = 0; j < ENC; j++) {
        float4 w = sW1t[j];
        float aj = sb1[j];
        aj = fmaf(enc.x, w.x, aj);
        aj = fmaf(enc.y, w.y, aj);
        aj = fmaf(enc.z, w.z, aj);
        aj = fmaf(enc.w, w.w, aj);
        aj = fmaxf(aj, 0.0f);
        unsigned long long aa = pk2(aj, aj);
        const ulonglong2* wr = (const ulonglong2*)&sWf[j * (D3 / 2)];
#pragma unroll
        for (int q = 0; q < 16; q++) {
            ulonglong2 ww = wr[q];
            h[2 * q]     = fma2(aa, ww.x, h[2 * q]);
            h[2 * q + 1] = fma2(aa, ww.y, h[2 * q + 1]);
        }
    }

    float z = sbm2[0];
#pragma unroll
    for (int p = 0; p < D3 / 2; p++) {
        float x, y;
        upk2(h[p], x, y);
        z = fmaf(fmaxf(x, 0.0f), sWm2[2 * p], z);
        z = fmaf(fmaxf(y, 0.0f), sWm2[2 * p + 1], z);
    }
    if (e < total) out[e] = z;
}

// ---------------- launch ----------------
extern "C" void kernel_launch(void* const* d_in, const int* in_sizes, int n_in,
                              void* d_out, int out_size) {
    const float* pos_table = (const float*)d_in[0];
    const float* node_feat = (const float*)d_in[1];
    const float* W1  = (const float*)d_in[2];
    const float* b1  = (const float*)d_in[3];
    const float* W2  = (const float*)d_in[4];
    const float* b2  = (const float*)d_in[5];
    const float* Wm1 = (const float*)d_in[6];
    const float* bm1 = (const float*)d_in[7];
    const float* Wm2 = (const float*)d_in[8];
    const float* bm2 = (const float*)d_in[9];
    const int* key_idx  = (const int*)d_in[10];
    const int* node_idx = (const int*)d_in[11];
    float* out = (float*)d_out;

    static bool attr_set = false;
    if (!attr_set) {
        cudaFuncSetAttribute(main_kernel, cudaFuncAttributeMaxDynamicSharedMemorySize, SMEM_BYTES);
        attr_set = true;
    }

    node_precompute_kernel<<<(NUM_NODES + 63) / 64, 256>>>(node_feat, Wm1, W2, b2, bm1);

    int total = out_size;
    int blocks = (total + 255) / 256;
    main_kernel<<<blocks, 256, SMEM_BYTES>>>(pos_table, key_idx, node_idx,
                                             W1, b1, Wm2, bm2, out, total);
}